// round 7
// baseline (speedup 1.0000x reference)
#include <cuda_runtime.h>
#include <cuda_fp16.h>
#include <cstdint>
#include <cstddef>

#define TT 64
#define BB 512
#define DD 512
#define HH 2048

// ---------------- scratch (device globals) ---------------------------------
__device__ __align__(16) float  g_ycur[BB * DD];
__device__ __align__(16) float  g_acc [BB * DD];
__device__ __align__(16) __half g_a   [BB * DD];          // gemm1 A operand
__device__ __align__(16) __half g_h   [(size_t)BB * HH];  // hidden activations
__device__ __align__(16) __half g_W1h [(size_t)DD * HH];
__device__ __align__(16) __half g_W2h [(size_t)HH * DD];
__device__ __align__(16) float  g_part[BB * DD];          // split-K partials
__device__ int g_flag[64];                                 // split-K handshakes

// ---------------- ptx helpers ----------------------------------------------
__device__ __forceinline__ uint32_t su32(const void* p) {
    return (uint32_t)__cvta_generic_to_shared(p);
}
#define CPA16(d, s) asm volatile("cp.async.cg.shared.global [%0], [%1], 16;" :: "r"(d), "l"(s))
#define CPC()       asm volatile("cp.async.commit_group;" ::: "memory")
#define WAITG(n)    asm volatile("cp.async.wait_group %0;" :: "n"(n) : "memory")

__device__ __forceinline__ void ldsm_x4(uint32_t a[4], uint32_t addr) {
    asm volatile("ldmatrix.sync.aligned.m8n8.x4.shared.b16 {%0,%1,%2,%3}, [%4];"
                 : "=r"(a[0]), "=r"(a[1]), "=r"(a[2]), "=r"(a[3]) : "r"(addr));
}
__device__ __forceinline__ void ldsm_x4_t(uint32_t a[4], uint32_t addr) {
    asm volatile("ldmatrix.sync.aligned.m8n8.x4.trans.shared.b16 {%0,%1,%2,%3}, [%4];"
                 : "=r"(a[0]), "=r"(a[1]), "=r"(a[2]), "=r"(a[3]) : "r"(addr));
}
__device__ __forceinline__ void mma_fp16(float c[4], const uint32_t a[4],
                                         uint32_t b0, uint32_t b1) {
    asm volatile(
        "mma.sync.aligned.m16n8k16.row.col.f32.f16.f16.f32 "
        "{%0,%1,%2,%3},{%4,%5,%6,%7},{%8,%9},{%0,%1,%2,%3};"
        : "+f"(c[0]), "+f"(c[1]), "+f"(c[2]), "+f"(c[3])
        : "r"(a[0]), "r"(a[1]), "r"(a[2]), "r"(a[3]), "r"(b0), "r"(b1));
}
__device__ __forceinline__ uint32_t packh2(float lo, float hi) {
    __half2 h = __floats2half2_rn(lo, hi);
    uint32_t u;
    __builtin_memcpy(&u, &h, 4);
    return u;
}

// ---------------- init / convert -------------------------------------------
__global__ void init_state(const float* __restrict__ y0, float* __restrict__ out) {
    int idx = blockIdx.x * blockDim.x + threadIdx.x;
    float4 v = ((const float4*)y0)[idx];
    ((float4*)out)[idx] = v;
    ((float4*)g_ycur)[idx] = v;
    __half2* a2 = (__half2*)g_a;
    a2[idx * 2]     = __floats2half2_rn(v.x, v.y);
    a2[idx * 2 + 1] = __floats2half2_rn(v.z, v.w);
}
__global__ void convert_w(const float* __restrict__ src, __half* __restrict__ dst) {
    int idx = blockIdx.x * blockDim.x + threadIdx.x;
    float4 v = ((const float4*)src)[idx];
    __half2* d2 = (__half2*)dst;
    d2[idx * 2]     = __floats2half2_rn(v.x, v.y);
    d2[idx * 2 + 1] = __floats2half2_rn(v.z, v.w);
}

extern __shared__ char dyn_sm[];

// ============================================================================
// GEMM1: g_h = tanh(g_a[512x512] @ W1[512x2048] + b1)
// CTA 64x128, 256 thr, warps 2x4 (wt 32x32), BK=64, 4-stage cp.async.
// ============================================================================
#define APIT 72          // A smem pitch (halves): 64 + 8 pad
#define BPIT1 136        // B smem pitch: 128 + 8 pad
#define ABY1 (64 * APIT * 2)
#define STG1 (ABY1 + 64 * BPIT1 * 2)      // 9216 + 17408 = 26624
#define SMEM1 (4 * STG1)                  // 106496
#define NT1 8

__global__ void __launch_bounds__(256, 1) gemm1_kernel(const float* __restrict__ b1) {
    const int tid = threadIdx.x, lane = tid & 31, warp = tid >> 5;
    const int g = lane >> 2, tg = lane & 3;
    const int wm = (warp >> 2) * 32, wn = (warp & 3) * 32;
    const int bm = blockIdx.y * 64, bn = blockIdx.x * 128;
    const int l16 = lane & 15, h16 = (lane >> 4) * 8;

    auto loadStage = [&](int st, int kt) {
        char* Ab = dyn_sm + st * STG1;
        char* Bb = Ab + ABY1;
#pragma unroll
        for (int l = 0; l < 2; l++) {
            int j = tid + l * 256, r = j >> 3, c = (j & 7) * 8;
            CPA16(su32(Ab + (r * APIT + c) * 2), g_a + (size_t)(bm + r) * DD + kt * 64 + c);
        }
#pragma unroll
        for (int l = 0; l < 4; l++) {
            int j = tid + l * 256, r = j >> 4, c = (j & 15) * 8;
            CPA16(su32(Bb + (r * BPIT1 + c) * 2), g_W1h + (size_t)(kt * 64 + r) * HH + bn + c);
        }
        CPC();
    };
    auto ldfA = [&](uint32_t Af[2][4], int st, int ks) {
        char* Ab = dyn_sm + st * STG1;
#pragma unroll
        for (int mi = 0; mi < 2; mi++)
            ldsm_x4(Af[mi], su32(Ab + ((wm + mi * 16 + l16) * APIT + ks + h16) * 2));
    };
    auto ldfB = [&](uint32_t Bf[4][2], int st, int ks) {
        char* Bb = dyn_sm + st * STG1 + ABY1;
#pragma unroll
        for (int bt = 0; bt < 2; bt++) {
            uint32_t r[4];
            ldsm_x4_t(r, su32(Bb + ((ks + l16) * BPIT1 + wn + bt * 16 + h16) * 2));
            Bf[bt * 2][0] = r[0]; Bf[bt * 2][1] = r[1];
            Bf[bt * 2 + 1][0] = r[2]; Bf[bt * 2 + 1][1] = r[3];
        }
    };

    loadStage(0, 0); loadStage(1, 1); loadStage(2, 2);
    WAITG(2);
    __syncthreads();

    float acc[2][4][4];
#pragma unroll
    for (int mi = 0; mi < 2; mi++)
#pragma unroll
        for (int ni = 0; ni < 4; ni++)
#pragma unroll
            for (int r = 0; r < 4; r++) acc[mi][ni][r] = 0.f;

    uint32_t Af[2][2][4], Bf[2][4][2];
    ldfA(Af[0], 0, 0); ldfB(Bf[0], 0, 0);

    for (int kt = 0; kt < NT1; kt++) {
        const int st = kt & 3;
#pragma unroll
        for (int ks = 0; ks < 4; ks++) {
            const int pb = ks & 1;
            if (ks == 3) { WAITG(1); __syncthreads(); }
            const int nst = (ks < 3) ? st : ((kt + 1) & 3);
            const int nks = (ks < 3) ? (ks + 1) * 16 : 0;
            if (ks < 3 || kt + 1 < NT1) {
                ldfA(Af[pb ^ 1], nst, nks);
                ldfB(Bf[pb ^ 1], nst, nks);
            }
#pragma unroll
            for (int mi = 0; mi < 2; mi++)
#pragma unroll
                for (int ni = 0; ni < 4; ni++)
                    mma_fp16(acc[mi][ni], Af[pb][mi], Bf[pb][ni][0], Bf[pb][ni][1]);
        }
        if (kt + 3 < NT1) loadStage((kt + 3) & 3, kt + 3); else CPC();
    }

    // epilogue: tanh(acc + b1) -> half2 stores
#pragma unroll
    for (int mi = 0; mi < 2; mi++)
#pragma unroll
        for (int ni = 0; ni < 4; ni++) {
            int col = bn + wn + ni * 8 + tg * 2;
            float bc0 = __ldg(b1 + col), bc1 = __ldg(b1 + col + 1);
#pragma unroll
            for (int hr = 0; hr < 2; hr++) {
                int row = bm + wm + mi * 16 + g + hr * 8;
                float v0 = tanhf(acc[mi][ni][hr * 2 + 0] + bc0);
                float v1 = tanhf(acc[mi][ni][hr * 2 + 1] + bc1);
                *(__half2*)&g_h[(size_t)row * HH + col] = __floats2half2_rn(v0, v1);
            }
        }
}

// ============================================================================
// GEMM2: C = g_h[512x2048] @ W2[2048x512]; split-K=2 across blockIdx.z,
// CTA 64x64, 256 thr, 8 warps = 2k x 2m x 2n (wt 32x32 per warp, k-split
// reduced via smem). kz=1 writes partial + flag; kz=0 adds + RK4 epilogue.
// ============================================================================
#define ABY2 (64 * APIT * 2)
#define STG2 (2 * ABY2)                   // A 9216 + B 9216 = 18432
#define SMEM2 (4 * STG2)                  // 73728
#define NT2 16

__global__ void __launch_bounds__(256, 1) gemm2_kernel(const float* __restrict__ b2,
                                                       const float* __restrict__ tarr,
                                                       float* __restrict__ out,
                                                       int s, float wgt, float cnext,
                                                       int first, int last) {
    const int tid = threadIdx.x, lane = tid & 31, warp = tid >> 5;
    const int g = lane >> 2, tg = lane & 3;
    const int kg = warp >> 2, w2 = warp & 3;
    const int wm = (w2 >> 1) * 32, wn = (w2 & 1) * 32;
    const int bm = blockIdx.y * 64, bn = blockIdx.x * 64;
    const int kz = blockIdx.z;
    const size_t kOff = (size_t)kz * 1024;
    const int l16 = lane & 15, h16 = (lane >> 4) * 8;
    const int kbase = kg * 32;

    auto loadStage = [&](int st, int kt) {
        char* Ab = dyn_sm + st * STG2;
        char* Bb = Ab + ABY2;
#pragma unroll
        for (int l = 0; l < 2; l++) {
            int j = tid + l * 256, r = j >> 3, c = (j & 7) * 8;
            CPA16(su32(Ab + (r * APIT + c) * 2),
                  g_h + (size_t)(bm + r) * HH + kOff + kt * 64 + c);
        }
#pragma unroll
        for (int l = 0; l < 2; l++) {
            int j = tid + l * 256, r = j >> 3, c = (j & 7) * 8;
            CPA16(su32(Bb + (r * APIT + c) * 2),
                  g_W2h + (kOff + kt * 64 + r) * DD + bn + c);
        }
        CPC();
    };
    auto ldfA = [&](uint32_t Af[2][4], int st, int ks) {
        char* Ab = dyn_sm + st * STG2;
#pragma unroll
        for (int mi = 0; mi < 2; mi++)
            ldsm_x4(Af[mi], su32(Ab + ((wm + mi * 16 + l16) * APIT + ks + h16) * 2));
    };
    auto ldfB = [&](uint32_t Bf[4][2], int st, int ks) {
        char* Bb = dyn_sm + st * STG2 + ABY2;
#pragma unroll
        for (int bt = 0; bt < 2; bt++) {
            uint32_t r[4];
            ldsm_x4_t(r, su32(Bb + ((ks + l16) * APIT + wn + bt * 16 + h16) * 2));
            Bf[bt * 2][0] = r[0]; Bf[bt * 2][1] = r[1];
            Bf[bt * 2 + 1][0] = r[2]; Bf[bt * 2 + 1][1] = r[3];
        }
    };

    loadStage(0, 0); loadStage(1, 1); loadStage(2, 2);
    WAITG(2);
    __syncthreads();

    float acc[2][4][4];
#pragma unroll
    for (int mi = 0; mi < 2; mi++)
#pragma unroll
        for (int ni = 0; ni < 4; ni++)
#pragma unroll
            for (int r = 0; r < 4; r++) acc[mi][ni][r] = 0.f;

    uint32_t Af[2][2][4], Bf[2][4][2];
    ldfA(Af[0], 0, kbase); ldfB(Bf[0], 0, kbase);

    for (int kt = 0; kt < NT2; kt++) {
        const int st = kt & 3;
#pragma unroll
        for (int l = 0; l < 2; l++) {
            const int pb = l & 1;
            if (l == 1) { WAITG(1); __syncthreads(); }
            const int nst = (l == 0) ? st : ((kt + 1) & 3);
            const int nks = (l == 0) ? (kbase + 16) : kbase;
            if (l == 0 || kt + 1 < NT2) {
                ldfA(Af[pb ^ 1], nst, nks);
                ldfB(Bf[pb ^ 1], nst, nks);
            }
#pragma unroll
            for (int mi = 0; mi < 2; mi++)
#pragma unroll
                for (int ni = 0; ni < 4; ni++)
                    mma_fp16(acc[mi][ni], Af[pb][mi], Bf[pb][ni][0], Bf[pb][ni][1]);
        }
        if (kt + 3 < NT2) loadStage((kt + 3) & 3, kt + 3); else CPC();
    }

    // ---- intra-CTA k-split reduction through smem (deterministic: kg0 + kg1)
    float* red = (float*)dyn_sm;   // 64 x 68 fp32 = 17408 B
    __syncthreads();
    if (kg == 1) {
#pragma unroll
        for (int mi = 0; mi < 2; mi++)
#pragma unroll
            for (int ni = 0; ni < 4; ni++)
#pragma unroll
                for (int r = 0; r < 4; r++) {
                    int rr = wm + mi * 16 + g + ((r >= 2) ? 8 : 0);
                    int cc = wn + ni * 8 + tg * 2 + (r & 1);
                    red[rr * 68 + cc] = acc[mi][ni][r];
                }
    }
    __syncthreads();
    if (kg == 0) {
#pragma unroll
        for (int mi = 0; mi < 2; mi++)
#pragma unroll
            for (int ni = 0; ni < 4; ni++)
#pragma unroll
                for (int r = 0; r < 4; r++) {
                    int rr = wm + mi * 16 + g + ((r >= 2) ? 8 : 0);
                    int cc = wn + ni * 8 + tg * 2 + (r & 1);
                    acc[mi][ni][r] += red[rr * 68 + cc];
                }
    }

    const int fid = blockIdx.y * 8 + blockIdx.x;

    if (kz == 1) {
        // publish partial, raise flag
        if (kg == 0) {
#pragma unroll
            for (int mi = 0; mi < 2; mi++)
#pragma unroll
                for (int ni = 0; ni < 4; ni++)
#pragma unroll
                    for (int r = 0; r < 4; r++) {
                        int row = bm + wm + mi * 16 + g + ((r >= 2) ? 8 : 0);
                        int col = bn + wn + ni * 8 + tg * 2 + (r & 1);
                        g_part[(size_t)row * DD + col] = acc[mi][ni][r];
                    }
        }
        __syncthreads();
        __threadfence();
        if (tid == 0) atomicExch(&g_flag[fid], 1);
        return;
    }

    // kz == 0: wait for peer, combine, RK4 epilogue
    if (tid == 0) {
        while (atomicCAS(&g_flag[fid], 1, 0) != 1) __nanosleep(64);
        __threadfence();
    }
    __syncthreads();

    if (kg == 0) {
        const float inv6 = 1.0f / 6.0f;
#pragma unroll
        for (int mi = 0; mi < 2; mi++) {
#pragma unroll
            for (int hr = 0; hr < 2; hr++) {
                int row = bm + wm + mi * 16 + g + hr * 8;
                float dt = __ldg(tarr + (size_t)(s + 1) * BB + row)
                         - __ldg(tarr + (size_t)s * BB + row);
#pragma unroll
                for (int ni = 0; ni < 4; ni++) {
#pragma unroll
                    for (int q = 0; q < 2; q++) {
                        int r = hr * 2 + q;
                        int col = bn + wn + ni * 8 + tg * 2 + q;
                        size_t off = (size_t)row * DD + col;
                        float sum = acc[mi][ni][r] + g_part[off];
                        float knew = dt * (sum + __ldg(b2 + col));
                        float a = first ? (wgt * knew) : (g_acc[off] + wgt * knew);
                        if (!last) {
                            g_acc[off] = a;
                            g_a[off] = __float2half(g_ycur[off] + cnext * knew);
                        } else {
                            float yn = g_ycur[off] + a * inv6;
                            g_ycur[off] = yn;
                            out[(size_t)(s + 1) * BB * DD + off] = yn;
                            g_a[off] = __float2half(yn);
                        }
                    }
                }
            }
        }
    }
}

// ---------------------------------------------------------------------------
extern "C" void kernel_launch(void* const* d_in, const int* in_sizes, int n_in,
                              void* d_out, int out_size) {
    const float* y0 = (const float*)d_in[0];
    const float* t  = (const float*)d_in[1];
    const float* W1 = (const float*)d_in[2];
    const float* b1 = (const float*)d_in[3];
    const float* W2 = (const float*)d_in[4];
    const float* b2 = (const float*)d_in[5];
    float* out = (float*)d_out;

    cudaFuncSetAttribute(gemm1_kernel, cudaFuncAttributeMaxDynamicSharedMemorySize, SMEM1);
    cudaFuncSetAttribute(gemm2_kernel, cudaFuncAttributeMaxDynamicSharedMemorySize, SMEM2);

    __half* w1h; cudaGetSymbolAddress((void**)&w1h, g_W1h);
    __half* w2h; cudaGetSymbolAddress((void**)&w2h, g_W2h);

    init_state<<<(BB * DD / 4) / 256, 256>>>(y0, out);
    convert_w<<<(DD * HH / 4) / 256, 256>>>(W1, w1h);
    convert_w<<<(HH * DD / 4) / 256, 256>>>(W2, w2h);

    const float ws[4] = {1.0f, 2.0f, 2.0f, 1.0f};
    const float cn[4] = {0.5f, 0.5f, 1.0f, 0.0f};

    dim3 grid1(HH / 128, BB / 64);     // 16 x 8 = 128 CTAs
    dim3 grid2(DD / 64, BB / 64, 2);   // 8 x 8 x 2 = 128 CTAs

    for (int s = 0; s < TT - 1; ++s) {
        for (int i = 0; i < 4; ++i) {
            gemm1_kernel<<<grid1, 256, SMEM1>>>(b1);
            gemm2_kernel<<<grid2, 256, SMEM2>>>(b2, t, out, s, ws[i], cn[i],
                                                (i == 0) ? 1 : 0, (i == 3) ? 1 : 0);
        }
    }
}